// round 1
// baseline (speedup 1.0000x reference)
#include <cuda_runtime.h>

#define BB      20000
#define NN      20
#define NODE_D  172
#define EDGE_D  172
#define TIME_D  100
#define QD      272          // NODE_D + TIME_D
#define KD      444          // NODE_D + EDGE_D + TIME_D
#define NH      2
#define HD      136
#define QT      (NH*KD)      // 888
#define ATTN_SCALE 0.08574929257125442f   // 136^-0.5
#define LN_EPS  1e-5f

// ---------------- scratch (__device__ globals: allocation-free) ----------------
__device__ float g_M [QT * QD];                 // folded Wk^T Wq  [888, 272]
__device__ float g_Rv[QD * QT];                 // folded Wr Wv    [272, 888]
__device__ float g_qt [(size_t)BB * QT];        // q-tilde         [B, 888]
__device__ float g_ctx[(size_t)BB * QT];        // context         [B, 888]
__device__ float g_x  [(size_t)BB * QD];        // pre-LN x        [B, 272]

// ---------------- K0a: M[o][c] = sum_d Wk[h*HD+d][j] * Wq[h*HD+d][c] ----------
__global__ void k_fold_M(const float* __restrict__ Wq, const float* __restrict__ Wk)
{
    int tid = blockIdx.x * blockDim.x + threadIdx.x;
    if (tid >= QT * QD) return;
    int c = tid % QD;
    int o = tid / QD;               // 0..887
    int h = o / KD, j = o % KD;
    const float* wk = Wk + (size_t)(h * HD) * KD + j;   // stride KD
    const float* wq = Wq + (size_t)(h * HD) * QD + c;   // stride QD
    float acc = 0.f;
#pragma unroll 8
    for (int d = 0; d < HD; ++d)
        acc += wk[(size_t)d * KD] * wq[(size_t)d * QD];
    g_M[tid] = acc;
}

// ---------------- K0b: Rv[o][p] = sum_d Wr[o][h*HD+d] * Wv[h*HD+d][j] ---------
__global__ void k_fold_Rv(const float* __restrict__ Wr, const float* __restrict__ Wv)
{
    int tid = blockIdx.x * blockDim.x + threadIdx.x;
    if (tid >= QD * QT) return;
    int p = tid % QT;
    int o = tid / QT;               // 0..271
    int h = p / KD, j = p % KD;
    const float* wr = Wr + (size_t)o * QD + h * HD;
    const float* wv = Wv + (size_t)(h * HD) * KD + j;
    float acc = 0.f;
#pragma unroll 8
    for (int d = 0; d < HD; ++d)
        acc += wr[d] * wv[(size_t)d * KD];
    g_Rv[tid] = acc;
}

// ---------------- K1: g_qt = q_in @ M^T   (M=B, N=888, K=272) -----------------
__global__ __launch_bounds__(256, 2)
void k_gemm_qt(const float* __restrict__ nodef, const float* __restrict__ ntime)
{
    __shared__ float As[8][128];
    __shared__ float Bs[8][128];
    const int t  = threadIdx.x;
    const int tx = t & 15, ty = t >> 4;
    const int bm = blockIdx.x, bn = blockIdx.y;
    const int lr = t >> 1;
    const int lk = (t & 1) * 4;
    const int arow = bm * 128 + lr;
    const int bcol = bn * 128 + lr;
    const bool aval = (arow < BB);
    const bool bval = (bcol < QT);

    float acc[8][8];
#pragma unroll
    for (int i = 0; i < 8; i++)
#pragma unroll
        for (int j = 0; j < 8; j++) acc[i][j] = 0.f;

    for (int kt = 0; kt < QD; kt += 8) {
        float4 av = make_float4(0.f, 0.f, 0.f, 0.f);
        float4 bv = make_float4(0.f, 0.f, 0.f, 0.f);
        const int ak = kt + lk;
        if (aval) {
            if (ak < NODE_D) av = *(const float4*)(nodef + (size_t)arow * NODE_D + ak);
            else             av = *(const float4*)(ntime + (size_t)arow * TIME_D + (ak - NODE_D));
        }
        if (bval) bv = *(const float4*)(g_M + (size_t)bcol * QD + kt + lk);
        __syncthreads();
        As[lk + 0][lr] = av.x; As[lk + 1][lr] = av.y;
        As[lk + 2][lr] = av.z; As[lk + 3][lr] = av.w;
        Bs[lk + 0][lr] = bv.x; Bs[lk + 1][lr] = bv.y;
        Bs[lk + 2][lr] = bv.z; Bs[lk + 3][lr] = bv.w;
        __syncthreads();
#pragma unroll
        for (int k = 0; k < 8; k++) {
            float4 a0 = *(const float4*)&As[k][ty * 8];
            float4 a1 = *(const float4*)&As[k][ty * 8 + 4];
            float4 b0 = *(const float4*)&Bs[k][tx * 8];
            float4 b1 = *(const float4*)&Bs[k][tx * 8 + 4];
            float a[8] = {a0.x, a0.y, a0.z, a0.w, a1.x, a1.y, a1.z, a1.w};
            float b[8] = {b0.x, b0.y, b0.z, b0.w, b1.x, b1.y, b1.z, b1.w};
#pragma unroll
            for (int i = 0; i < 8; i++)
#pragma unroll
                for (int j = 0; j < 8; j++) acc[i][j] += a[i] * b[j];
        }
    }

#pragma unroll
    for (int i = 0; i < 8; i++) {
        int r = bm * 128 + ty * 8 + i;
        if (r >= BB) continue;
        int c0 = bn * 128 + tx * 8;
        if (c0 < QT)
            *(float4*)(g_qt + (size_t)r * QT + c0) =
                make_float4(acc[i][0], acc[i][1], acc[i][2], acc[i][3]);
        if (c0 + 4 < QT)
            *(float4*)(g_qt + (size_t)r * QT + c0 + 4) =
                make_float4(acc[i][4], acc[i][5], acc[i][6], acc[i][7]);
    }
}

// ---------------- K2: streaming attention, one CTA per root row ---------------
__global__ __launch_bounds__(256)
void k_attn(const float* __restrict__ nbr_node, const float* __restrict__ nbr_time,
            const float* __restrict__ nbr_edge, const int* __restrict__ masks,
            float* __restrict__ out)
{
    __shared__ __align__(16) float kv[NN * KD];   // 20 x 444 = 35520 B
    __shared__ __align__(16) float qts[QT];       // 888
    __shared__ float sc[NH * NN];                 // 40

    const int b = blockIdx.x;
    const int t = threadIdx.x;

    // stage kv = concat(node[172], edge[172], time[100]) per neighbor
    for (int i = t; i < NN * (NODE_D / 4); i += 256) {
        int n = i / (NODE_D / 4), j4 = i % (NODE_D / 4);
        float4 v = *(const float4*)(nbr_node + ((size_t)b * NN + n) * NODE_D + j4 * 4);
        *(float4*)&kv[n * KD + j4 * 4] = v;
    }
    for (int i = t; i < NN * (EDGE_D / 4); i += 256) {
        int n = i / (EDGE_D / 4), j4 = i % (EDGE_D / 4);
        float4 v = *(const float4*)(nbr_edge + ((size_t)b * NN + n) * EDGE_D + j4 * 4);
        *(float4*)&kv[n * KD + NODE_D + j4 * 4] = v;
    }
    for (int i = t; i < NN * (TIME_D / 4); i += 256) {
        int n = i / (TIME_D / 4), j4 = i % (TIME_D / 4);
        float4 v = *(const float4*)(nbr_time + ((size_t)b * NN + n) * TIME_D + j4 * 4);
        *(float4*)&kv[n * KD + NODE_D + EDGE_D + j4 * 4] = v;
    }
    for (int i = t; i < QT / 4; i += 256)
        *(float4*)&qts[i * 4] = *(const float4*)(g_qt + (size_t)b * QT + i * 4);
    __syncthreads();

    // scores: 40 (h,n) pairs across 8 warps
    const int w = t >> 5, lane = t & 31;
    for (int p = w; p < NH * NN; p += 8) {
        int h = p / NN, n = p % NN;
        float s = 0.f;
        for (int j = lane; j < KD; j += 32) s += qts[h * KD + j] * kv[n * KD + j];
#pragma unroll
        for (int o = 16; o; o >>= 1) s += __shfl_xor_sync(0xffffffffu, s, o);
        if (lane == 0)
            sc[p] = (masks[(size_t)b * NN + n] == 0) ? -1e10f : s * ATTN_SCALE;
    }
    __syncthreads();

    // softmax: warp h handles head h
    if (w < NH) {
        const int h = w;
        float x = (lane < NN) ? sc[h * NN + lane] : -INFINITY;
        float m = x;
#pragma unroll
        for (int o = 16; o; o >>= 1) m = fmaxf(m, __shfl_xor_sync(0xffffffffu, m, o));
        float e = (lane < NN) ? __expf(x - m) : 0.f;
        float ssum = e;
#pragma unroll
        for (int o = 16; o; o >>= 1) ssum += __shfl_xor_sync(0xffffffffu, ssum, o);
        float a = e / ssum;
        if (lane < NN) {
            sc[h * NN + lane] = a;
            out[(size_t)BB * QD + ((size_t)b * NH + h) * NN + lane] = a;
        }
    }
    __syncthreads();

    // ctx_h[j] = sum_n attn[h,n] * kv[n][j]
    for (int jj = t; jj < QT; jj += 256) {
        int h = jj / KD, j = jj % KD;
        float accv = 0.f;
#pragma unroll
        for (int n = 0; n < NN; ++n) accv += sc[h * NN + n] * kv[n * KD + j];
        g_ctx[(size_t)b * QT + jj] = accv;
    }
}

// ---------------- K3: g_x = ctx @ Rv^T + br + residual  (M=B,N=272,K=888) -----
__global__ __launch_bounds__(256, 2)
void k_gemm_out(const float* __restrict__ nodef, const float* __restrict__ ntime,
                const float* __restrict__ br)
{
    __shared__ float As[8][128];
    __shared__ float Bs[8][128];
    const int t  = threadIdx.x;
    const int tx = t & 15, ty = t >> 4;
    const int bm = blockIdx.x, bn = blockIdx.y;
    const int lr = t >> 1;
    const int lk = (t & 1) * 4;
    const int arow = bm * 128 + lr;
    const int bcol = bn * 128 + lr;
    const bool aval = (arow < BB);
    const bool bval = (bcol < QD);

    float acc[8][8];
#pragma unroll
    for (int i = 0; i < 8; i++)
#pragma unroll
        for (int j = 0; j < 8; j++) acc[i][j] = 0.f;

    for (int kt = 0; kt < QT; kt += 8) {
        float4 av = make_float4(0.f, 0.f, 0.f, 0.f);
        float4 bv = make_float4(0.f, 0.f, 0.f, 0.f);
        if (aval) av = *(const float4*)(g_ctx + (size_t)arow * QT + kt + lk);
        if (bval) bv = *(const float4*)(g_Rv  + (size_t)bcol * QT + kt + lk);
        __syncthreads();
        As[lk + 0][lr] = av.x; As[lk + 1][lr] = av.y;
        As[lk + 2][lr] = av.z; As[lk + 3][lr] = av.w;
        Bs[lk + 0][lr] = bv.x; Bs[lk + 1][lr] = bv.y;
        Bs[lk + 2][lr] = bv.z; Bs[lk + 3][lr] = bv.w;
        __syncthreads();
#pragma unroll
        for (int k = 0; k < 8; k++) {
            float4 a0 = *(const float4*)&As[k][ty * 8];
            float4 a1 = *(const float4*)&As[k][ty * 8 + 4];
            float4 b0 = *(const float4*)&Bs[k][tx * 8];
            float4 b1 = *(const float4*)&Bs[k][tx * 8 + 4];
            float a[8] = {a0.x, a0.y, a0.z, a0.w, a1.x, a1.y, a1.z, a1.w};
            float b[8] = {b0.x, b0.y, b0.z, b0.w, b1.x, b1.y, b1.z, b1.w};
#pragma unroll
            for (int i = 0; i < 8; i++)
#pragma unroll
                for (int j = 0; j < 8; j++) acc[i][j] += a[i] * b[j];
        }
    }

#pragma unroll
    for (int i = 0; i < 8; i++) {
        int r = bm * 128 + ty * 8 + i;
        if (r >= BB) continue;
        int c0 = bn * 128 + tx * 8;
#pragma unroll
        for (int half = 0; half < 2; half++) {
            int c = c0 + half * 4;
            if (c >= QD) continue;
            float4 resid;
            if (c < NODE_D) resid = *(const float4*)(nodef + (size_t)r * NODE_D + c);
            else            resid = *(const float4*)(ntime + (size_t)r * TIME_D + (c - NODE_D));
            float4 bb = *(const float4*)(br + c);
            float4 v;
            v.x = acc[i][half * 4 + 0] + bb.x + resid.x;
            v.y = acc[i][half * 4 + 1] + bb.y + resid.y;
            v.z = acc[i][half * 4 + 2] + bb.z + resid.z;
            v.w = acc[i][half * 4 + 3] + bb.w + resid.w;
            *(float4*)(g_x + (size_t)r * QD + c) = v;
        }
    }
}

// ---------------- K4: LayerNorm, one warp per row -----------------------------
__global__ __launch_bounds__(256)
void k_ln(const float* __restrict__ gamma, const float* __restrict__ beta,
          float* __restrict__ out)
{
    int gw   = (blockIdx.x * blockDim.x + threadIdx.x) >> 5;
    int lane = threadIdx.x & 31;
    if (gw >= BB) return;
    const float* x = g_x + (size_t)gw * QD;
    float s = 0.f, s2 = 0.f;
    for (int j = lane; j < QD; j += 32) { float v = x[j]; s += v; s2 += v * v; }
#pragma unroll
    for (int o = 16; o; o >>= 1) {
        s  += __shfl_xor_sync(0xffffffffu, s,  o);
        s2 += __shfl_xor_sync(0xffffffffu, s2, o);
    }
    float mu   = s * (1.f / QD);
    float var  = s2 * (1.f / QD) - mu * mu;
    float rstd = rsqrtf(var + LN_EPS);
    for (int j = lane; j < QD; j += 32)
        out[(size_t)gw * QD + j] = (x[j] - mu) * rstd * gamma[j] + beta[j];
}

// ---------------- launch ------------------------------------------------------
extern "C" void kernel_launch(void* const* d_in, const int* in_sizes, int n_in,
                              void* d_out, int out_size)
{
    const float* nodef    = (const float*)d_in[0];
    const float* ntime    = (const float*)d_in[1];
    const float* nbr_node = (const float*)d_in[2];
    const float* nbr_time = (const float*)d_in[3];
    const float* nbr_edge = (const float*)d_in[4];
    const int*   masks    = (const int*)  d_in[5];
    const float* Wq       = (const float*)d_in[6];
    const float* Wk       = (const float*)d_in[7];
    const float* Wv       = (const float*)d_in[8];
    const float* Wr       = (const float*)d_in[9];
    const float* br       = (const float*)d_in[10];
    const float* gamma    = (const float*)d_in[11];
    const float* beta     = (const float*)d_in[12];
    float* out = (float*)d_out;

    k_fold_M <<<(QT * QD + 255) / 256, 256>>>(Wq, Wk);
    k_fold_Rv<<<(QD * QT + 255) / 256, 256>>>(Wr, Wv);

    dim3 g1((BB + 127) / 128, (QT + 127) / 128);
    k_gemm_qt<<<g1, 256>>>(nodef, ntime);

    k_attn<<<BB, 256>>>(nbr_node, nbr_time, nbr_edge, masks, out);

    dim3 g3((BB + 127) / 128, (QD + 127) / 128);
    k_gemm_out<<<g3, 256>>>(nodef, ntime, br);

    k_ln<<<(BB * 32 + 255) / 256, 256>>>(gamma, beta, out);
}

// round 5
// speedup vs baseline: 1.7559x; 1.7559x over previous
#include <cuda_runtime.h>
#include <cuda_bf16.h>
#include <cstdint>

#define BB      20000
#define NN      20
#define NODE_D  172
#define EDGE_D  172
#define TIME_D  100
#define QD      272          // NODE_D + TIME_D
#define KD      444          // NODE_D + EDGE_D + TIME_D
#define NH      2
#define HD      136
#define QT      (NH*KD)      // 888
#define ATTN_SCALE 0.08574929257125442f   // 136^-0.5
#define LN_EPS  1e-5f

// GEMM geometry (K-chunk = 32 bf16)
#define KPAD1   288          // GEMM1 K (272 -> 9 chunks)
#define NPAD1   896          // GEMM1 N (888 -> 7 tiles of 128)
#define KPAD2   896          // GEMM2 K (888 -> 28 chunks)
#define NPAD2   288          // GEMM2 N (272 -> 3 tiles of 96)
#define NCHUNK1 9
#define NCHUNK2 28

// smem row stride: 40 bf16 = 80 B (16B-aligned, ldmatrix-friendly)
#define RSTR    40

// ---------------- scratch -----------------------------------------------------
__device__ __align__(16) __nv_bfloat16 g_qin_hi[(size_t)BB * KPAD1];
__device__ __align__(16) __nv_bfloat16 g_qin_lo[(size_t)BB * KPAD1];
__device__ __align__(16) __nv_bfloat16 g_Mhi[NPAD1 * KPAD1];
__device__ __align__(16) __nv_bfloat16 g_Mlo[NPAD1 * KPAD1];
__device__ __align__(16) __nv_bfloat16 g_Rvhi[NPAD2 * KPAD2];
__device__ __align__(16) __nv_bfloat16 g_Rvlo[NPAD2 * KPAD2];
__device__ __align__(16) float         g_qt[(size_t)BB * NPAD1];
__device__ __align__(16) __nv_bfloat16 g_cxh[(size_t)BB * KPAD2];
__device__ __align__(16) __nv_bfloat16 g_cxl[(size_t)BB * KPAD2];
__device__ __align__(16) float         g_x[(size_t)BB * QD];

// ---------------- helpers -----------------------------------------------------
__device__ __forceinline__ uint32_t smem_u32(const void* p) {
    uint32_t a;
    asm("{ .reg .u64 t; cvta.to.shared.u64 t, %1; cvt.u32.u64 %0, t; }" : "=r"(a) : "l"(p));
    return a;
}
__device__ __forceinline__ void cp16(uint32_t dst, const void* src, bool v) {
    int sz = v ? 16 : 0;
    asm volatile("cp.async.cg.shared.global [%0], [%1], 16, %2;"
                 :: "r"(dst), "l"(src), "r"(sz));
}
#define CP_COMMIT() asm volatile("cp.async.commit_group;" ::: "memory")
#define CP_WAIT(n)  asm volatile("cp.async.wait_group %0;" :: "n"(n) : "memory")

#define LDM_X4(r, a) \
    asm volatile("ldmatrix.sync.aligned.m8n8.x4.shared.b16 {%0,%1,%2,%3}, [%4];" \
                 : "=r"((r)[0]), "=r"((r)[1]), "=r"((r)[2]), "=r"((r)[3]) : "r"(a))

__device__ __forceinline__ void mma_bf16(float* c, const uint32_t a[4],
                                         uint32_t b0, uint32_t b1) {
    asm volatile(
        "mma.sync.aligned.m16n8k16.row.col.f32.bf16.bf16.f32 "
        "{%0,%1,%2,%3}, {%4,%5,%6,%7}, {%8,%9}, {%0,%1,%2,%3};"
        : "+f"(c[0]), "+f"(c[1]), "+f"(c[2]), "+f"(c[3])
        : "r"(a[0]), "r"(a[1]), "r"(a[2]), "r"(a[3]), "r"(b0), "r"(b1));
}

__device__ __forceinline__ void split_bf16(float x, __nv_bfloat16& h, __nv_bfloat16& l) {
    h = __float2bfloat16(x);
    l = __float2bfloat16(x - __bfloat162float(h));
}

// ---------------- prep: qin = concat(nodef, ntime) -> hi/lo bf16 [B, 288] -----
__global__ void k_prep_qin(const float* __restrict__ nodef, const float* __restrict__ ntime)
{
    int i = blockIdx.x * blockDim.x + threadIdx.x;
    if (i >= BB * KPAD1) return;
    int r = i / KPAD1, c = i % KPAD1;
    float x = 0.f;
    if (c < NODE_D)   x = nodef[(size_t)r * NODE_D + c];
    else if (c < QD)  x = ntime[(size_t)r * TIME_D + (c - NODE_D)];
    __nv_bfloat16 h, l; split_bf16(x, h, l);
    g_qin_hi[i] = h; g_qin_lo[i] = l;
}

// ---------------- fold M = Wk^T Wq per head -> hi/lo [896, 288] ---------------
__global__ void k_fold_M(const float* __restrict__ Wq, const float* __restrict__ Wk)
{
    int tid = blockIdx.x * blockDim.x + threadIdx.x;
    if (tid >= NPAD1 * KPAD1) return;
    int c = tid % KPAD1;
    int o = tid / KPAD1;
    float acc = 0.f;
    if (o < QT && c < QD) {
        int h = o / KD, j = o % KD;
        const float* wk = Wk + (size_t)(h * HD) * KD + j;
        const float* wq = Wq + (size_t)(h * HD) * QD + c;
#pragma unroll 8
        for (int d = 0; d < HD; ++d)
            acc += wk[(size_t)d * KD] * wq[(size_t)d * QD];
    }
    __nv_bfloat16 h16, l16; split_bf16(acc, h16, l16);
    g_Mhi[tid] = h16; g_Mlo[tid] = l16;
}

// ---------------- fold Rv = Wr Wv per head -> hi/lo [288, 896] ----------------
__global__ void k_fold_Rv(const float* __restrict__ Wr, const float* __restrict__ Wv)
{
    int tid = blockIdx.x * blockDim.x + threadIdx.x;
    if (tid >= NPAD2 * KPAD2) return;
    int p = tid % KPAD2;
    int o = tid / KPAD2;
    float acc = 0.f;
    if (o < QD && p < QT) {
        int h = p / KD, j = p % KD;
        const float* wr = Wr + (size_t)o * QD + h * HD;
        const float* wv = Wv + (size_t)(h * HD) * KD + j;
#pragma unroll 8
        for (int d = 0; d < HD; ++d)
            acc += wr[d] * wv[(size_t)d * KD];
    }
    __nv_bfloat16 h16, l16; split_bf16(acc, h16, l16);
    g_Rvhi[tid] = h16; g_Rvlo[tid] = l16;
}

// ---------------- bf16x3 HMMA GEMM --------------------------------------------
// C[B, N] = A[B, K] @ Bmat[N, K]^T, split hi/lo, 3 passes.
// Block tile 128 x BN, 8 warps (4 M x 2 N), warp tile 32 x (BN/2), K-chunk 32.
// WHICH=1: GEMM1 (qin x M -> g_qt). WHICH=2: GEMM2 (ctx x Rv -> g_x, fused).
template<int BN, int NCH, int KP, int OSTR, bool FUSE, int WHICH>
__global__ __launch_bounds__(256)
void k_gemm_mma(const float* __restrict__ nodef, const float* __restrict__ ntime,
                const float* __restrict__ br)
{
    // resolve scratch pointers DEVICE-SIDE (host-passed __device__ symbols are invalid)
    const __nv_bfloat16* __restrict__ Ah = (WHICH == 1) ? g_qin_hi : g_cxh;
    const __nv_bfloat16* __restrict__ Al = (WHICH == 1) ? g_qin_lo : g_cxl;
    const __nv_bfloat16* __restrict__ Bh = (WHICH == 1) ? g_Mhi : g_Rvhi;
    const __nv_bfloat16* __restrict__ Bl = (WHICH == 1) ? g_Mlo : g_Rvlo;
    float* __restrict__ outp             = (WHICH == 1) ? g_qt : g_x;

    constexpr int WN   = BN / 2;       // warp N tile
    constexpr int WNS  = WN / 8;       // n sub-tiles per warp
    constexpr int NG   = WN / 16;      // ldmatrix groups per warp
    constexpr int OFF_AL = 128 * 2 * RSTR;            // bytes
    constexpr int OFF_BH = 2 * OFF_AL;
    constexpr int OFF_BL = OFF_BH + BN * 2 * RSTR;
    constexpr int STRIDE = OFF_BL + BN * 2 * RSTR;    // per-buffer bytes

    extern __shared__ char sm[];
    const uint32_t S = smem_u32(sm);
    const int t = threadIdx.x, lane = t & 31, wid = t >> 5;
    const int warpM = wid & 3, warpN = wid >> 2;
    const int bm = blockIdx.x, bn = blockIdx.y;

    float acc[2][WNS][4];
#pragma unroll
    for (int i = 0; i < 2; i++)
#pragma unroll
        for (int j = 0; j < WNS; j++)
#pragma unroll
            for (int q = 0; q < 4; q++) acc[i][j][q] = 0.f;

    auto load_chunk = [&](int c, int b) {
        const uint32_t base = S + b * STRIDE;
        // A tile 128 x 32 (hi + lo)
        for (int i = t; i < 512; i += 256) {
            int row = i >> 2, seg = i & 3;
            int gr = bm * 128 + row;
            bool v = gr < BB;
            int grc = v ? gr : (BB - 1);
            size_t off = (size_t)grc * KP + c * 32 + seg * 8;
            cp16(base + row * 80 + seg * 16, Ah + off, v);
            cp16(base + OFF_AL + row * 80 + seg * 16, Al + off, v);
        }
        // B tile BN x 32 (hi + lo)
        for (int i = t; i < BN * 4; i += 256) {
            int row = i >> 2, seg = i & 3;
            size_t off = (size_t)(bn * BN + row) * KP + c * 32 + seg * 8;
            cp16(base + OFF_BH + row * 80 + seg * 16, Bh + off, true);
            cp16(base + OFF_BL + row * 80 + seg * 16, Bl + off, true);
        }
        CP_COMMIT();
    };

    load_chunk(0, 0);

    for (int c = 0; c < NCH; c++) {
        if (c + 1 < NCH) { load_chunk(c + 1, (c + 1) & 1); CP_WAIT(1); }
        else             { CP_WAIT(0); }
        __syncthreads();

        const uint32_t base = S + (c & 1) * STRIDE;
        const uint32_t lrow = lane & 15;
        const uint32_t lcol = (lane >> 4) * 16;   // bytes (8 bf16)

#pragma unroll
        for (int kk = 0; kk < 2; kk++) {
            const uint32_t kb = kk * 32 + lcol;   // byte offset in row
            uint32_t a_hi[2][4], a_lo[2][4];
#pragma unroll
            for (int ms = 0; ms < 2; ms++) {
                uint32_t r0 = (warpM * 32 + ms * 16 + lrow) * 80 + kb;
                LDM_X4(a_hi[ms], base + r0);
                LDM_X4(a_lo[ms], base + OFF_AL + r0);
            }
#pragma unroll
            for (int ng = 0; ng < NG; ng++) {
                uint32_t bh[4], bl[4];
                uint32_t r0 = (warpN * WN + ng * 16 + lrow) * 80 + kb;
                LDM_X4(bh, base + OFF_BH + r0);
                LDM_X4(bl, base + OFF_BL + r0);
#pragma unroll
                for (int ms = 0; ms < 2; ms++) {
                    mma_bf16(acc[ms][2*ng],   a_hi[ms], bh[0], bh[2]);
                    mma_bf16(acc[ms][2*ng+1], a_hi[ms], bh[1], bh[3]);
                    mma_bf16(acc[ms][2*ng],   a_hi[ms], bl[0], bl[2]);
                    mma_bf16(acc[ms][2*ng+1], a_hi[ms], bl[1], bl[3]);
                    mma_bf16(acc[ms][2*ng],   a_lo[ms], bh[0], bh[2]);
                    mma_bf16(acc[ms][2*ng+1], a_lo[ms], bh[1], bh[3]);
                }
            }
        }
        __syncthreads();
    }

    // epilogue: direct float2 stores from fragments
    const int g = lane >> 2, tq = lane & 3;
#pragma unroll
    for (int ms = 0; ms < 2; ms++) {
#pragma unroll
        for (int ns = 0; ns < WNS; ns++) {
            int row = bm * 128 + warpM * 32 + ms * 16 + g;
            int col = bn * BN + warpN * WN + ns * 8 + tq * 2;
#pragma unroll
            for (int half = 0; half < 2; half++) {
                int r = row + half * 8;
                if (r >= BB) continue;
                float v0 = acc[ms][ns][half * 2 + 0];
                float v1 = acc[ms][ns][half * 2 + 1];
                if (FUSE) {
                    if (col >= QD) continue;
                    float2 res;
                    if (col < NODE_D) res = *(const float2*)(nodef + (size_t)r * NODE_D + col);
                    else              res = *(const float2*)(ntime + (size_t)r * TIME_D + (col - NODE_D));
                    float2 bb = *(const float2*)(br + col);
                    v0 += bb.x + res.x;
                    v1 += bb.y + res.y;
                }
                *(float2*)(outp + (size_t)r * OSTR + col) = make_float2(v0, v1);
            }
        }
    }
}

// ---------------- K2: streaming attention, one CTA per root row ---------------
__global__ __launch_bounds__(256)
void k_attn(const float* __restrict__ nbr_node, const float* __restrict__ nbr_time,
            const float* __restrict__ nbr_edge, const int* __restrict__ masks,
            float* __restrict__ out)
{
    __shared__ __align__(16) float kv[NN * KD];
    __shared__ __align__(16) float qts[QT];
    __shared__ float sc[NH * NN];

    const int b = blockIdx.x;
    const int t = threadIdx.x;

    for (int i = t; i < NN * (NODE_D / 4); i += 256) {
        int n = i / (NODE_D / 4), j4 = i % (NODE_D / 4);
        *(float4*)&kv[n * KD + j4 * 4] = *(const float4*)(nbr_node + ((size_t)b * NN + n) * NODE_D + j4 * 4);
    }
    for (int i = t; i < NN * (EDGE_D / 4); i += 256) {
        int n = i / (EDGE_D / 4), j4 = i % (EDGE_D / 4);
        *(float4*)&kv[n * KD + NODE_D + j4 * 4] = *(const float4*)(nbr_edge + ((size_t)b * NN + n) * EDGE_D + j4 * 4);
    }
    for (int i = t; i < NN * (TIME_D / 4); i += 256) {
        int n = i / (TIME_D / 4), j4 = i % (TIME_D / 4);
        *(float4*)&kv[n * KD + NODE_D + EDGE_D + j4 * 4] = *(const float4*)(nbr_time + ((size_t)b * NN + n) * TIME_D + j4 * 4);
    }
    for (int i = t; i < QT / 4; i += 256)
        *(float4*)&qts[i * 4] = *(const float4*)(g_qt + (size_t)b * NPAD1 + i * 4);
    __syncthreads();

    const int w = t >> 5, lane = t & 31;
    for (int p = w; p < NH * NN; p += 8) {
        int h = p / NN, n = p % NN;
        float s = 0.f;
        for (int j = lane; j < KD; j += 32) s += qts[h * KD + j] * kv[n * KD + j];
#pragma unroll
        for (int o = 16; o; o >>= 1) s += __shfl_xor_sync(0xffffffffu, s, o);
        if (lane == 0)
            sc[p] = (masks[(size_t)b * NN + n] == 0) ? -1e10f : s * ATTN_SCALE;
    }
    __syncthreads();

    if (w < NH) {
        const int h = w;
        float x = (lane < NN) ? sc[h * NN + lane] : -INFINITY;
        float m = x;
#pragma unroll
        for (int o = 16; o; o >>= 1) m = fmaxf(m, __shfl_xor_sync(0xffffffffu, m, o));
        float e = (lane < NN) ? __expf(x - m) : 0.f;
        float ssum = e;
#pragma unroll
        for (int o = 16; o; o >>= 1) ssum += __shfl_xor_sync(0xffffffffu, ssum, o);
        float a = e / ssum;
        if (lane < NN) {
            sc[h * NN + lane] = a;
            out[(size_t)BB * QD + ((size_t)b * NH + h) * NN + lane] = a;
        }
    }
    __syncthreads();

    for (int jj = t; jj < KPAD2; jj += 256) {
        float accv = 0.f;
        if (jj < QT) {
            int h = jj / KD, j = jj % KD;
#pragma unroll
            for (int n = 0; n < NN; ++n) accv += sc[h * NN + n] * kv[n * KD + j];
        }
        __nv_bfloat16 h16 = __float2bfloat16(accv);
        g_cxh[(size_t)b * KPAD2 + jj] = h16;
        g_cxl[(size_t)b * KPAD2 + jj] = __float2bfloat16(accv - __bfloat162float(h16));
    }
}

// ---------------- LayerNorm, one warp per row ---------------------------------
__global__ __launch_bounds__(256)
void k_ln(const float* __restrict__ gamma, const float* __restrict__ beta,
          float* __restrict__ out)
{
    int gw   = (blockIdx.x * blockDim.x + threadIdx.x) >> 5;
    int lane = threadIdx.x & 31;
    if (gw >= BB) return;
    const float* x = g_x + (size_t)gw * QD;
    float s = 0.f, s2 = 0.f;
    for (int j = lane; j < QD; j += 32) { float v = x[j]; s += v; s2 += v * v; }
#pragma unroll
    for (int o = 16; o; o >>= 1) {
        s  += __shfl_xor_sync(0xffffffffu, s,  o);
        s2 += __shfl_xor_sync(0xffffffffu, s2, o);
    }
    float mu   = s * (1.f / QD);
    float var  = s2 * (1.f / QD) - mu * mu;
    float rstd = rsqrtf(var + LN_EPS);
    for (int j = lane; j < QD; j += 32)
        out[(size_t)gw * QD + j] = (x[j] - mu) * rstd * gamma[j] + beta[j];
}

// ---------------- launch ------------------------------------------------------
#define SMEM1 (2 * (4 * 128 * 2 * RSTR))                            // 81920
#define SMEM2 (2 * (2 * 128 * 2 * RSTR + 2 * 96 * 2 * RSTR))        // 71680

extern "C" void kernel_launch(void* const* d_in, const int* in_sizes, int n_in,
                              void* d_out, int out_size)
{
    const float* nodef    = (const float*)d_in[0];
    const float* ntime    = (const float*)d_in[1];
    const float* nbr_node = (const float*)d_in[2];
    const float* nbr_time = (const float*)d_in[3];
    const float* nbr_edge = (const float*)d_in[4];
    const int*   masks    = (const int*)  d_in[5];
    const float* Wq       = (const float*)d_in[6];
    const float* Wk       = (const float*)d_in[7];
    const float* Wv       = (const float*)d_in[8];
    const float* Wr       = (const float*)d_in[9];
    const float* br       = (const float*)d_in[10];
    const float* gamma    = (const float*)d_in[11];
    const float* beta     = (const float*)d_in[12];
    float* out = (float*)d_out;

    auto g1 = k_gemm_mma<128, NCHUNK1, KPAD1, NPAD1, false, 1>;
    auto g2 = k_gemm_mma<96,  NCHUNK2, KPAD2, QD,    true,  2>;
    cudaFuncSetAttribute(g1, cudaFuncAttributeMaxDynamicSharedMemorySize, SMEM1);
    cudaFuncSetAttribute(g2, cudaFuncAttributeMaxDynamicSharedMemorySize, SMEM2);

    k_prep_qin<<<(BB * KPAD1 + 255) / 256, 256>>>(nodef, ntime);
    k_fold_M <<<(NPAD1 * KPAD1 + 255) / 256, 256>>>(Wq, Wk);
    k_fold_Rv<<<(NPAD2 * KPAD2 + 255) / 256, 256>>>(Wr, Wv);

    dim3 grid1((BB + 127) / 128, NPAD1 / 128);
    g1<<<grid1, 256, SMEM1>>>(nodef, ntime, br);

    k_attn<<<BB, 256>>>(nbr_node, nbr_time, nbr_edge, masks, out);

    dim3 grid2((BB + 127) / 128, NPAD2 / 96);
    g2<<<grid2, 256, SMEM2>>>(nodef, ntime, br);

    k_ln<<<(BB * 32 + 255) / 256, 256>>>(gamma, beta, out);
}

// round 6
// speedup vs baseline: 2.1421x; 1.2199x over previous
#include <cuda_runtime.h>
#include <cuda_bf16.h>
#include <cstdint>

#define BB      20000
#define NN      20
#define NODE_D  172
#define EDGE_D  172
#define TIME_D  100
#define QD      272          // NODE_D + TIME_D
#define KD      444          // NODE_D + EDGE_D + TIME_D
#define NH      2
#define HD      136
#define QT      (NH*KD)      // 888
#define ATTN_SCALE 0.08574929257125442f   // 136^-0.5
#define LN_EPS  1e-5f

// GEMM geometry (K-chunk = 32 bf16)
#define KPAD1   288          // GEMM1 K (272 -> 9 chunks)
#define NPAD1   896          // GEMM1 N (888 -> 7 tiles of 128)
#define KPAD2   896          // GEMM2 K (888 -> 28 chunks)
#define NPAD2   288          // GEMM2 N (272 -> 3 tiles of 96)
#define NCHUNK1 9
#define NCHUNK2 28

// smem row stride: 40 bf16 = 80 B (16B-aligned, ldmatrix-friendly)
#define RSTR    40

// ---------------- scratch -----------------------------------------------------
__device__ __align__(16) __nv_bfloat16 g_qin_hi[(size_t)BB * KPAD1];
__device__ __align__(16) __nv_bfloat16 g_qin_lo[(size_t)BB * KPAD1];
__device__ __align__(16) __nv_bfloat16 g_Mhi[NPAD1 * KPAD1];
__device__ __align__(16) __nv_bfloat16 g_Mlo[NPAD1 * KPAD1];
__device__ __align__(16) __nv_bfloat16 g_Rvhi[NPAD2 * KPAD2];
__device__ __align__(16) __nv_bfloat16 g_Rvlo[NPAD2 * KPAD2];
__device__ __align__(16) float         g_qt[(size_t)BB * NPAD1];
__device__ __align__(16) __nv_bfloat16 g_cxh[(size_t)BB * KPAD2];
__device__ __align__(16) __nv_bfloat16 g_cxl[(size_t)BB * KPAD2];
__device__ __align__(16) float         g_x[(size_t)BB * QD];

// ---------------- helpers -----------------------------------------------------
__device__ __forceinline__ uint32_t smem_u32(const void* p) {
    uint32_t a;
    asm("{ .reg .u64 t; cvta.to.shared.u64 t, %1; cvt.u32.u64 %0, t; }" : "=r"(a) : "l"(p));
    return a;
}
__device__ __forceinline__ void cp16(uint32_t dst, const void* src, bool v) {
    int sz = v ? 16 : 0;
    asm volatile("cp.async.cg.shared.global [%0], [%1], 16, %2;"
                 :: "r"(dst), "l"(src), "r"(sz));
}
#define CP_COMMIT() asm volatile("cp.async.commit_group;" ::: "memory")
#define CP_WAIT(n)  asm volatile("cp.async.wait_group %0;" :: "n"(n) : "memory")

#define LDM_X4(r, a) \
    asm volatile("ldmatrix.sync.aligned.m8n8.x4.shared.b16 {%0,%1,%2,%3}, [%4];" \
                 : "=r"((r)[0]), "=r"((r)[1]), "=r"((r)[2]), "=r"((r)[3]) : "r"(a))

__device__ __forceinline__ void mma_bf16(float* c, const uint32_t a[4],
                                         uint32_t b0, uint32_t b1) {
    asm volatile(
        "mma.sync.aligned.m16n8k16.row.col.f32.bf16.bf16.f32 "
        "{%0,%1,%2,%3}, {%4,%5,%6,%7}, {%8,%9}, {%0,%1,%2,%3};"
        : "+f"(c[0]), "+f"(c[1]), "+f"(c[2]), "+f"(c[3])
        : "r"(a[0]), "r"(a[1]), "r"(a[2]), "r"(a[3]), "r"(b0), "r"(b1));
}

__device__ __forceinline__ void split_bf16(float x, __nv_bfloat16& h, __nv_bfloat16& l) {
    h = __float2bfloat16(x);
    l = __float2bfloat16(x - __bfloat162float(h));
}

// ---------------- prep: qin = concat(nodef, ntime) -> hi/lo bf16 [B, 288] -----
__global__ void k_prep_qin(const float* __restrict__ nodef, const float* __restrict__ ntime)
{
    int i = blockIdx.x * blockDim.x + threadIdx.x;
    if (i >= BB * KPAD1) return;
    int r = i / KPAD1, c = i % KPAD1;
    float x = 0.f;
    if (c < NODE_D)   x = nodef[(size_t)r * NODE_D + c];
    else if (c < QD)  x = ntime[(size_t)r * TIME_D + (c - NODE_D)];
    __nv_bfloat16 h, l; split_bf16(x, h, l);
    g_qin_hi[i] = h; g_qin_lo[i] = l;
}

// ---------------- fold M = Wk^T Wq per head -> hi/lo [896, 288] ---------------
__global__ void k_fold_M(const float* __restrict__ Wq, const float* __restrict__ Wk)
{
    int tid = blockIdx.x * blockDim.x + threadIdx.x;
    if (tid >= NPAD1 * KPAD1) return;
    int c = tid % KPAD1;
    int o = tid / KPAD1;
    float acc = 0.f;
    if (o < QT && c < QD) {
        int h = o / KD, j = o % KD;
        const float* wk = Wk + (size_t)(h * HD) * KD + j;
        const float* wq = Wq + (size_t)(h * HD) * QD + c;
#pragma unroll 8
        for (int d = 0; d < HD; ++d)
            acc += wk[(size_t)d * KD] * wq[(size_t)d * QD];
    }
    __nv_bfloat16 h16, l16; split_bf16(acc, h16, l16);
    g_Mhi[tid] = h16; g_Mlo[tid] = l16;
}

// ---------------- fold Rv = Wr Wv per head -> hi/lo [288, 896] ----------------
__global__ void k_fold_Rv(const float* __restrict__ Wr, const float* __restrict__ Wv)
{
    int tid = blockIdx.x * blockDim.x + threadIdx.x;
    if (tid >= NPAD2 * KPAD2) return;
    int p = tid % KPAD2;
    int o = tid / KPAD2;
    float acc = 0.f;
    if (o < QD && p < QT) {
        int h = p / KD, j = p % KD;
        const float* wr = Wr + (size_t)o * QD + h * HD;
        const float* wv = Wv + (size_t)(h * HD) * KD + j;
#pragma unroll 8
        for (int d = 0; d < HD; ++d)
            acc += wr[d] * wv[(size_t)d * KD];
    }
    __nv_bfloat16 h16, l16; split_bf16(acc, h16, l16);
    g_Rvhi[tid] = h16; g_Rvlo[tid] = l16;
}

// ---------------- bf16x3 HMMA GEMM --------------------------------------------
template<int BN, int NCH, int KP, int OSTR, bool FUSE, int WHICH>
__global__ __launch_bounds__(256)
void k_gemm_mma(const float* __restrict__ nodef, const float* __restrict__ ntime,
                const float* __restrict__ br)
{
    const __nv_bfloat16* __restrict__ Ah = (WHICH == 1) ? g_qin_hi : g_cxh;
    const __nv_bfloat16* __restrict__ Al = (WHICH == 1) ? g_qin_lo : g_cxl;
    const __nv_bfloat16* __restrict__ Bh = (WHICH == 1) ? g_Mhi : g_Rvhi;
    const __nv_bfloat16* __restrict__ Bl = (WHICH == 1) ? g_Mlo : g_Rvlo;
    float* __restrict__ outp             = (WHICH == 1) ? g_qt : g_x;

    constexpr int WN   = BN / 2;
    constexpr int WNS  = WN / 8;
    constexpr int NG   = WN / 16;
    constexpr int OFF_AL = 128 * 2 * RSTR;
    constexpr int OFF_BH = 2 * OFF_AL;
    constexpr int OFF_BL = OFF_BH + BN * 2 * RSTR;
    constexpr int STRIDE = OFF_BL + BN * 2 * RSTR;

    extern __shared__ char sm[];
    const uint32_t S = smem_u32(sm);
    const int t = threadIdx.x, lane = t & 31, wid = t >> 5;
    const int warpM = wid & 3, warpN = wid >> 2;
    const int bm = blockIdx.x, bn = blockIdx.y;

    float acc[2][WNS][4];
#pragma unroll
    for (int i = 0; i < 2; i++)
#pragma unroll
        for (int j = 0; j < WNS; j++)
#pragma unroll
            for (int q = 0; q < 4; q++) acc[i][j][q] = 0.f;

    auto load_chunk = [&](int c, int b) {
        const uint32_t base = S + b * STRIDE;
        for (int i = t; i < 512; i += 256) {
            int row = i >> 2, seg = i & 3;
            int gr = bm * 128 + row;
            bool v = gr < BB;
            int grc = v ? gr : (BB - 1);
            size_t off = (size_t)grc * KP + c * 32 + seg * 8;
            cp16(base + row * 80 + seg * 16, Ah + off, v);
            cp16(base + OFF_AL + row * 80 + seg * 16, Al + off, v);
        }
        for (int i = t; i < BN * 4; i += 256) {
            int row = i >> 2, seg = i & 3;
            size_t off = (size_t)(bn * BN + row) * KP + c * 32 + seg * 8;
            cp16(base + OFF_BH + row * 80 + seg * 16, Bh + off, true);
            cp16(base + OFF_BL + row * 80 + seg * 16, Bl + off, true);
        }
        CP_COMMIT();
    };

    load_chunk(0, 0);

    for (int c = 0; c < NCH; c++) {
        if (c + 1 < NCH) { load_chunk(c + 1, (c + 1) & 1); CP_WAIT(1); }
        else             { CP_WAIT(0); }
        __syncthreads();

        const uint32_t base = S + (c & 1) * STRIDE;
        const uint32_t lrow = lane & 15;
        const uint32_t lcol = (lane >> 4) * 16;

#pragma unroll
        for (int kk = 0; kk < 2; kk++) {
            const uint32_t kb = kk * 32 + lcol;
            uint32_t a_hi[2][4], a_lo[2][4];
#pragma unroll
            for (int ms = 0; ms < 2; ms++) {
                uint32_t r0 = (warpM * 32 + ms * 16 + lrow) * 80 + kb;
                LDM_X4(a_hi[ms], base + r0);
                LDM_X4(a_lo[ms], base + OFF_AL + r0);
            }
#pragma unroll
            for (int ng = 0; ng < NG; ng++) {
                uint32_t bh[4], bl[4];
                uint32_t r0 = (warpN * WN + ng * 16 + lrow) * 80 + kb;
                LDM_X4(bh, base + OFF_BH + r0);
                LDM_X4(bl, base + OFF_BL + r0);
#pragma unroll
                for (int ms = 0; ms < 2; ms++) {
                    mma_bf16(acc[ms][2*ng],   a_hi[ms], bh[0], bh[2]);
                    mma_bf16(acc[ms][2*ng+1], a_hi[ms], bh[1], bh[3]);
                    mma_bf16(acc[ms][2*ng],   a_hi[ms], bl[0], bl[2]);
                    mma_bf16(acc[ms][2*ng+1], a_hi[ms], bl[1], bl[3]);
                    mma_bf16(acc[ms][2*ng],   a_lo[ms], bh[0], bh[2]);
                    mma_bf16(acc[ms][2*ng+1], a_lo[ms], bh[1], bh[3]);
                }
            }
        }
        __syncthreads();
    }

    const int g = lane >> 2, tq = lane & 3;
#pragma unroll
    for (int ms = 0; ms < 2; ms++) {
#pragma unroll
        for (int ns = 0; ns < WNS; ns++) {
            int row = bm * 128 + warpM * 32 + ms * 16 + g;
            int col = bn * BN + warpN * WN + ns * 8 + tq * 2;
#pragma unroll
            for (int half = 0; half < 2; half++) {
                int r = row + half * 8;
                if (r >= BB) continue;
                float v0 = acc[ms][ns][half * 2 + 0];
                float v1 = acc[ms][ns][half * 2 + 1];
                if (FUSE) {
                    if (col >= QD) continue;
                    float2 res;
                    if (col < NODE_D) res = *(const float2*)(nodef + (size_t)r * NODE_D + col);
                    else              res = *(const float2*)(ntime + (size_t)r * TIME_D + (col - NODE_D));
                    float2 bb = *(const float2*)(br + col);
                    v0 += bb.x + res.x;
                    v1 += bb.y + res.y;
                }
                *(float2*)(outp + (size_t)r * OSTR + col) = make_float2(v0, v1);
            }
        }
    }
}

// ---------------- K2: streaming attention, one CTA per root row ---------------
// 320 threads / 10 warps. Warp w owns neighbors {2w, 2w+1}; kv read ONCE in the
// score phase (both heads per pass) and ONCE in the ctx phase (both heads).
__global__ __launch_bounds__(320)
void k_attn(const float* __restrict__ nbr_node, const float* __restrict__ nbr_time,
            const float* __restrict__ nbr_edge, const int* __restrict__ masks,
            float* __restrict__ out)
{
    __shared__ __align__(16) float kv[NN * KD];   // 35520 B
    __shared__ __align__(16) float qts[QT];       // 3552 B
    __shared__ float sc[NH * NN];

    const int b = blockIdx.x;
    const int t = threadIdx.x;
    const int w = t >> 5, lane = t & 31;
    const uint32_t kvS  = smem_u32(kv);
    const uint32_t qtsS = smem_u32(qts);

    // ---- stage kv + qts via cp.async (all float4-granular) ----
    for (int i = t; i < NN * (NODE_D / 4); i += 320) {
        int n = i / (NODE_D / 4), j4 = i % (NODE_D / 4);
        cp16(kvS + (n * KD + j4 * 4) * 4,
             nbr_node + ((size_t)b * NN + n) * NODE_D + j4 * 4, true);
    }
    for (int i = t; i < NN * (EDGE_D / 4); i += 320) {
        int n = i / (EDGE_D / 4), j4 = i % (EDGE_D / 4);
        cp16(kvS + (n * KD + NODE_D + j4 * 4) * 4,
             nbr_edge + ((size_t)b * NN + n) * EDGE_D + j4 * 4, true);
    }
    for (int i = t; i < NN * (TIME_D / 4); i += 320) {
        int n = i / (TIME_D / 4), j4 = i % (TIME_D / 4);
        cp16(kvS + (n * KD + NODE_D + EDGE_D + j4 * 4) * 4,
             nbr_time + ((size_t)b * NN + n) * TIME_D + j4 * 4, true);
    }
    for (int i = t; i < QT / 4; i += 320)
        cp16(qtsS + i * 16, g_qt + (size_t)b * NPAD1 + i * 4, true);
    CP_COMMIT();
    CP_WAIT(0);
    __syncthreads();

    // ---- scores: warp w -> neighbors n0=2w, n1=2w+1, both heads in one pass --
    {
        const int n0 = 2 * w, n1 = 2 * w + 1;
        float a00 = 0.f, a01 = 0.f, a10 = 0.f, a11 = 0.f;
        for (int j = lane; j < KD; j += 32) {
            float q0 = qts[j], q1 = qts[KD + j];
            float k0 = kv[n0 * KD + j], k1 = kv[n1 * KD + j];
            a00 += q0 * k0; a01 += q0 * k1;
            a10 += q1 * k0; a11 += q1 * k1;
        }
#pragma unroll
        for (int o = 16; o; o >>= 1) {
            a00 += __shfl_xor_sync(0xffffffffu, a00, o);
            a01 += __shfl_xor_sync(0xffffffffu, a01, o);
            a10 += __shfl_xor_sync(0xffffffffu, a10, o);
            a11 += __shfl_xor_sync(0xffffffffu, a11, o);
        }
        if (lane == 0) {
            int m0 = masks[(size_t)b * NN + n0];
            int m1 = masks[(size_t)b * NN + n1];
            sc[n0]      = (m0 == 0) ? -1e10f : a00 * ATTN_SCALE;
            sc[n1]      = (m1 == 0) ? -1e10f : a01 * ATTN_SCALE;
            sc[NN + n0] = (m0 == 0) ? -1e10f : a10 * ATTN_SCALE;
            sc[NN + n1] = (m1 == 0) ? -1e10f : a11 * ATTN_SCALE;
        }
    }
    __syncthreads();

    // ---- softmax: warp h handles head h; write attn output ----
    if (w < NH) {
        const int h = w;
        float x = (lane < NN) ? sc[h * NN + lane] : -INFINITY;
        float m = x;
#pragma unroll
        for (int o = 16; o; o >>= 1) m = fmaxf(m, __shfl_xor_sync(0xffffffffu, m, o));
        float e = (lane < NN) ? __expf(x - m) : 0.f;
        float ssum = e;
#pragma unroll
        for (int o = 16; o; o >>= 1) ssum += __shfl_xor_sync(0xffffffffu, ssum, o);
        float a = e / ssum;
        if (lane < NN) {
            sc[h * NN + lane] = a;
            out[(size_t)BB * QD + ((size_t)b * NH + h) * NN + lane] = a;
        }
    }
    __syncthreads();

    // ---- ctx: one pass over kv, both heads per element ----
    for (int j = t; j < KD; j += 320) {
        float c0 = 0.f, c1 = 0.f;
#pragma unroll
        for (int n = 0; n < NN; ++n) {
            float kvv = kv[n * KD + j];
            c0 += sc[n] * kvv;
            c1 += sc[NN + n] * kvv;
        }
        __nv_bfloat16 h0 = __float2bfloat16(c0);
        __nv_bfloat16 h1 = __float2bfloat16(c1);
        size_t base = (size_t)b * KPAD2;
        g_cxh[base + j]      = h0;
        g_cxl[base + j]      = __float2bfloat16(c0 - __bfloat162float(h0));
        g_cxh[base + KD + j] = h1;
        g_cxl[base + KD + j] = __float2bfloat16(c1 - __bfloat162float(h1));
    }
    if (t < KPAD2 - QT) {   // zero the 888..895 padding
        g_cxh[(size_t)b * KPAD2 + QT + t] = __float2bfloat16(0.f);
        g_cxl[(size_t)b * KPAD2 + QT + t] = __float2bfloat16(0.f);
    }
}

// ---------------- LayerNorm, one warp per row ---------------------------------
__global__ __launch_bounds__(256)
void k_ln(const float* __restrict__ gamma, const float* __restrict__ beta,
          float* __restrict__ out)
{
    int gw   = (blockIdx.x * blockDim.x + threadIdx.x) >> 5;
    int lane = threadIdx.x & 31;
    if (gw >= BB) return;
    const float* x = g_x + (size_t)gw * QD;
    float s = 0.f, s2 = 0.f;
    for (int j = lane; j < QD; j += 32) { float v = x[j]; s += v; s2 += v * v; }
#pragma unroll
    for (int o = 16; o; o >>= 1) {
        s  += __shfl_xor_sync(0xffffffffu, s,  o);
        s2 += __shfl_xor_sync(0xffffffffu, s2, o);
    }
    float mu   = s * (1.f / QD);
    float var  = s2 * (1.f / QD) - mu * mu;
    float rstd = rsqrtf(var + LN_EPS);
    for (int j = lane; j < QD; j += 32)
        out[(size_t)gw * QD + j] = (x[j] - mu) * rstd * gamma[j] + beta[j];
}

// ---------------- launch ------------------------------------------------------
#define SMEM1 (2 * (4 * 128 * 2 * RSTR))                            // 81920
#define SMEM2 (2 * (2 * 128 * 2 * RSTR + 2 * 96 * 2 * RSTR))        // 71680

extern "C" void kernel_launch(void* const* d_in, const int* in_sizes, int n_in,
                              void* d_out, int out_size)
{
    const float* nodef    = (const float*)d_in[0];
    const float* ntime    = (const float*)d_in[1];
    const float* nbr_node = (const float*)d_in[2];
    const float* nbr_time = (const float*)d_in[3];
    const float* nbr_edge = (const float*)d_in[4];
    const int*   masks    = (const int*)  d_in[5];
    const float* Wq       = (const float*)d_in[6];
    const float* Wk       = (const float*)d_in[7];
    const float* Wv       = (const float*)d_in[8];
    const float* Wr       = (const float*)d_in[9];
    const float* br       = (const float*)d_in[10];
    const float* gamma    = (const float*)d_in[11];
    const float* beta     = (const float*)d_in[12];
    float* out = (float*)d_out;

    auto g1 = k_gemm_mma<128, NCHUNK1, KPAD1, NPAD1, false, 1>;
    auto g2 = k_gemm_mma<96,  NCHUNK2, KPAD2, QD,    true,  2>;
    cudaFuncSetAttribute(g1, cudaFuncAttributeMaxDynamicSharedMemorySize, SMEM1);
    cudaFuncSetAttribute(g2, cudaFuncAttributeMaxDynamicSharedMemorySize, SMEM2);

    k_prep_qin<<<(BB * KPAD1 + 255) / 256, 256>>>(nodef, ntime);
    k_fold_M <<<(NPAD1 * KPAD1 + 255) / 256, 256>>>(Wq, Wk);
    k_fold_Rv<<<(NPAD2 * KPAD2 + 255) / 256, 256>>>(Wr, Wv);

    dim3 grid1((BB + 127) / 128, NPAD1 / 128);
    g1<<<grid1, 256, SMEM1>>>(nodef, ntime, br);

    k_attn<<<BB, 320>>>(nbr_node, nbr_time, nbr_edge, masks, out);

    dim3 grid2((BB + 127) / 128, NPAD2 / 96);
    g2<<<grid2, 256, SMEM2>>>(nodef, ntime, br);

    k_ln<<<(BB * 32 + 255) / 256, 256>>>(gamma, beta, out);
}

// round 7
// speedup vs baseline: 2.1423x; 1.0001x over previous
#include <cuda_runtime.h>
#include <cuda_bf16.h>
#include <cstdint>

#define BB      20000
#define NN      20
#define NODE_D  172
#define EDGE_D  172
#define TIME_D  100
#define QD      272          // NODE_D + TIME_D
#define KD      444          // NODE_D + EDGE_D + TIME_D
#define NH      2
#define HD      136
#define QT      (NH*KD)      // 888
#define ATTN_SCALE 0.08574929257125442f   // 136^-0.5
#define LN_EPS  1e-5f

// GEMM geometry (K-chunk = 32 bf16)
#define KPAD1   288          // GEMM1 K (272 -> 9 chunks)
#define NPAD1   896          // GEMM1 N (888 -> 7 tiles of 128)
#define KPAD2   896          // GEMM2 K (888 -> 28 chunks)
#define NPAD2   288          // GEMM2 N (272 -> 3 tiles of 96)
#define NCHUNK1 9
#define NCHUNK2 28

// smem row stride: 40 bf16 = 80 B (16B-aligned, ldmatrix-friendly)
#define RSTR    40

// ---------------- scratch -----------------------------------------------------
__device__ __align__(16) __nv_bfloat16 g_qin_hi[(size_t)BB * KPAD1];
__device__ __align__(16) __nv_bfloat16 g_qin_lo[(size_t)BB * KPAD1];
__device__ __align__(16) __nv_bfloat16 g_Mhi[NPAD1 * KPAD1];
__device__ __align__(16) __nv_bfloat16 g_Mlo[NPAD1 * KPAD1];
__device__ __align__(16) __nv_bfloat16 g_Rvhi[NPAD2 * KPAD2];
__device__ __align__(16) __nv_bfloat16 g_Rvlo[NPAD2 * KPAD2];
__device__ __align__(16) float         g_qt[(size_t)BB * NPAD1];
__device__ __align__(16) __nv_bfloat16 g_cxh[(size_t)BB * KPAD2];
__device__ __align__(16) __nv_bfloat16 g_cxl[(size_t)BB * KPAD2];
__device__ __align__(16) float         g_x[(size_t)BB * QD];

// ---------------- helpers -----------------------------------------------------
__device__ __forceinline__ uint32_t smem_u32(const void* p) {
    uint32_t a;
    asm("{ .reg .u64 t; cvta.to.shared.u64 t, %1; cvt.u32.u64 %0, t; }" : "=r"(a) : "l"(p));
    return a;
}
__device__ __forceinline__ void cp16(uint32_t dst, const void* src, bool v) {
    int sz = v ? 16 : 0;
    asm volatile("cp.async.cg.shared.global [%0], [%1], 16, %2;"
                 :: "r"(dst), "l"(src), "r"(sz));
}
#define CP_COMMIT() asm volatile("cp.async.commit_group;" ::: "memory")
#define CP_WAIT(n)  asm volatile("cp.async.wait_group %0;" :: "n"(n) : "memory")

#define LDM_X4(r, a) \
    asm volatile("ldmatrix.sync.aligned.m8n8.x4.shared.b16 {%0,%1,%2,%3}, [%4];" \
                 : "=r"((r)[0]), "=r"((r)[1]), "=r"((r)[2]), "=r"((r)[3]) : "r"(a))

__device__ __forceinline__ void mma_bf16(float* c, const uint32_t a[4],
                                         uint32_t b0, uint32_t b1) {
    asm volatile(
        "mma.sync.aligned.m16n8k16.row.col.f32.bf16.bf16.f32 "
        "{%0,%1,%2,%3}, {%4,%5,%6,%7}, {%8,%9}, {%0,%1,%2,%3};"
        : "+f"(c[0]), "+f"(c[1]), "+f"(c[2]), "+f"(c[3])
        : "r"(a[0]), "r"(a[1]), "r"(a[2]), "r"(a[3]), "r"(b0), "r"(b1));
}

__device__ __forceinline__ void split_bf16(float x, __nv_bfloat16& h, __nv_bfloat16& l) {
    h = __float2bfloat16(x);
    l = __float2bfloat16(x - __bfloat162float(h));
}

// ---------------- prep: qin = concat(nodef, ntime) -> hi/lo bf16 [B, 288] -----
__global__ void k_prep_qin(const float* __restrict__ nodef, const float* __restrict__ ntime)
{
    int i = blockIdx.x * blockDim.x + threadIdx.x;
    if (i >= BB * KPAD1) return;
    int r = i / KPAD1, c = i % KPAD1;
    float x = 0.f;
    if (c < NODE_D)   x = nodef[(size_t)r * NODE_D + c];
    else if (c < QD)  x = ntime[(size_t)r * TIME_D + (c - NODE_D)];
    __nv_bfloat16 h, l; split_bf16(x, h, l);
    g_qin_hi[i] = h; g_qin_lo[i] = l;
}

// ---------------- fold M = Wk^T Wq per head -> hi/lo [896, 288] ---------------
__global__ void k_fold_M(const float* __restrict__ Wq, const float* __restrict__ Wk)
{
    int tid = blockIdx.x * blockDim.x + threadIdx.x;
    if (tid >= NPAD1 * KPAD1) return;
    int c = tid % KPAD1;
    int o = tid / KPAD1;
    float acc = 0.f;
    if (o < QT && c < QD) {
        int h = o / KD, j = o % KD;
        const float* wk = Wk + (size_t)(h * HD) * KD + j;
        const float* wq = Wq + (size_t)(h * HD) * QD + c;
#pragma unroll 8
        for (int d = 0; d < HD; ++d)
            acc += wk[(size_t)d * KD] * wq[(size_t)d * QD];
    }
    __nv_bfloat16 h16, l16; split_bf16(acc, h16, l16);
    g_Mhi[tid] = h16; g_Mlo[tid] = l16;
}

// ---------------- fold Rv = Wr Wv per head -> hi/lo [288, 896] ----------------
__global__ void k_fold_Rv(const float* __restrict__ Wr, const float* __restrict__ Wv)
{
    int tid = blockIdx.x * blockDim.x + threadIdx.x;
    if (tid >= NPAD2 * KPAD2) return;
    int p = tid % KPAD2;
    int o = tid / KPAD2;
    float acc = 0.f;
    if (o < QD && p < QT) {
        int h = p / KD, j = p % KD;
        const float* wr = Wr + (size_t)o * QD + h * HD;
        const float* wv = Wv + (size_t)(h * HD) * KD + j;
#pragma unroll 8
        for (int d = 0; d < HD; ++d)
            acc += wr[d] * wv[(size_t)d * KD];
    }
    __nv_bfloat16 h16, l16; split_bf16(acc, h16, l16);
    g_Rvhi[tid] = h16; g_Rvlo[tid] = l16;
}

// ---------------- bf16x3 HMMA GEMM --------------------------------------------
// Inner loop ordered pass-major (hh, hl, lh) x ms so dependent MMAs to the same
// accumulator are separated by 3 independent MMAs (RAW-stall relief).
template<int BN, int NCH, int KP, int OSTR, bool FUSE, int WHICH>
__global__ __launch_bounds__(256)
void k_gemm_mma(const float* __restrict__ nodef, const float* __restrict__ ntime,
                const float* __restrict__ br)
{
    const __nv_bfloat16* __restrict__ Ah = (WHICH == 1) ? g_qin_hi : g_cxh;
    const __nv_bfloat16* __restrict__ Al = (WHICH == 1) ? g_qin_lo : g_cxl;
    const __nv_bfloat16* __restrict__ Bh = (WHICH == 1) ? g_Mhi : g_Rvhi;
    const __nv_bfloat16* __restrict__ Bl = (WHICH == 1) ? g_Mlo : g_Rvlo;
    float* __restrict__ outp             = (WHICH == 1) ? g_qt : g_x;

    constexpr int WN   = BN / 2;
    constexpr int WNS  = WN / 8;
    constexpr int NG   = WN / 16;
    constexpr int OFF_AL = 128 * 2 * RSTR;
    constexpr int OFF_BH = 2 * OFF_AL;
    constexpr int OFF_BL = OFF_BH + BN * 2 * RSTR;
    constexpr int STRIDE = OFF_BL + BN * 2 * RSTR;

    extern __shared__ char sm[];
    const uint32_t S = smem_u32(sm);
    const int t = threadIdx.x, lane = t & 31, wid = t >> 5;
    const int warpM = wid & 3, warpN = wid >> 2;
    const int bm = blockIdx.x, bn = blockIdx.y;

    float acc[2][WNS][4];
#pragma unroll
    for (int i = 0; i < 2; i++)
#pragma unroll
        for (int j = 0; j < WNS; j++)
#pragma unroll
            for (int q = 0; q < 4; q++) acc[i][j][q] = 0.f;

    auto load_chunk = [&](int c, int b) {
        const uint32_t base = S + b * STRIDE;
        for (int i = t; i < 512; i += 256) {
            int row = i >> 2, seg = i & 3;
            int gr = bm * 128 + row;
            bool v = gr < BB;
            int grc = v ? gr : (BB - 1);
            size_t off = (size_t)grc * KP + c * 32 + seg * 8;
            cp16(base + row * 80 + seg * 16, Ah + off, v);
            cp16(base + OFF_AL + row * 80 + seg * 16, Al + off, v);
        }
        for (int i = t; i < BN * 4; i += 256) {
            int row = i >> 2, seg = i & 3;
            size_t off = (size_t)(bn * BN + row) * KP + c * 32 + seg * 8;
            cp16(base + OFF_BH + row * 80 + seg * 16, Bh + off, true);
            cp16(base + OFF_BL + row * 80 + seg * 16, Bl + off, true);
        }
        CP_COMMIT();
    };

    load_chunk(0, 0);

    for (int c = 0; c < NCH; c++) {
        if (c + 1 < NCH) { load_chunk(c + 1, (c + 1) & 1); CP_WAIT(1); }
        else             { CP_WAIT(0); }
        __syncthreads();

        const uint32_t base = S + (c & 1) * STRIDE;
        const uint32_t lrow = lane & 15;
        const uint32_t lcol = (lane >> 4) * 16;

#pragma unroll
        for (int kk = 0; kk < 2; kk++) {
            const uint32_t kb = kk * 32 + lcol;
            uint32_t a_hi[2][4], a_lo[2][4];
#pragma unroll
            for (int ms = 0; ms < 2; ms++) {
                uint32_t r0 = (warpM * 32 + ms * 16 + lrow) * 80 + kb;
                LDM_X4(a_hi[ms], base + r0);
                LDM_X4(a_lo[ms], base + OFF_AL + r0);
            }
#pragma unroll
            for (int ng = 0; ng < NG; ng++) {
                uint32_t bh[4], bl[4];
                uint32_t r0 = (warpN * WN + ng * 16 + lrow) * 80 + kb;
                LDM_X4(bh, base + OFF_BH + r0);
                LDM_X4(bl, base + OFF_BL + r0);
                // pass-major order: same-acc dependents separated by 3 MMAs
#pragma unroll
                for (int ms = 0; ms < 2; ms++) {
                    mma_bf16(acc[ms][2*ng],   a_hi[ms], bh[0], bh[2]);
                    mma_bf16(acc[ms][2*ng+1], a_hi[ms], bh[1], bh[3]);
                }
#pragma unroll
                for (int ms = 0; ms < 2; ms++) {
                    mma_bf16(acc[ms][2*ng],   a_hi[ms], bl[0], bl[2]);
                    mma_bf16(acc[ms][2*ng+1], a_hi[ms], bl[1], bl[3]);
                }
#pragma unroll
                for (int ms = 0; ms < 2; ms++) {
                    mma_bf16(acc[ms][2*ng],   a_lo[ms], bh[0], bh[2]);
                    mma_bf16(acc[ms][2*ng+1], a_lo[ms], bh[1], bh[3]);
                }
            }
        }
        __syncthreads();
    }

    const int g = lane >> 2, tq = lane & 3;
#pragma unroll
    for (int ms = 0; ms < 2; ms++) {
#pragma unroll
        for (int ns = 0; ns < WNS; ns++) {
            int row = bm * 128 + warpM * 32 + ms * 16 + g;
            int col = bn * BN + warpN * WN + ns * 8 + tq * 2;
#pragma unroll
            for (int half = 0; half < 2; half++) {
                int r = row + half * 8;
                if (r >= BB) continue;
                float v0 = acc[ms][ns][half * 2 + 0];
                float v1 = acc[ms][ns][half * 2 + 1];
                if (FUSE) {
                    if (col >= QD) continue;
                    float2 res;
                    if (col < NODE_D) res = *(const float2*)(nodef + (size_t)r * NODE_D + col);
                    else              res = *(const float2*)(ntime + (size_t)r * TIME_D + (col - NODE_D));
                    float2 bb = *(const float2*)(br + col);
                    v0 += bb.x + res.x;
                    v1 += bb.y + res.y;
                }
                *(float2*)(outp + (size_t)r * OSTR + col) = make_float2(v0, v1);
            }
        }
    }
}

// ---------------- K2: streaming attention, one CTA per root row ---------------
__global__ __launch_bounds__(320)
void k_attn(const float* __restrict__ nbr_node, const float* __restrict__ nbr_time,
            const float* __restrict__ nbr_edge, const int* __restrict__ masks,
            float* __restrict__ out)
{
    __shared__ __align__(16) float kv[NN * KD];   // 35520 B
    __shared__ __align__(16) float qts[QT];       // 3552 B
    __shared__ float sc[NH * NN];

    const int b = blockIdx.x;
    const int t = threadIdx.x;
    const int w = t >> 5, lane = t & 31;
    const uint32_t kvS  = smem_u32(kv);
    const uint32_t qtsS = smem_u32(qts);

    for (int i = t; i < NN * (NODE_D / 4); i += 320) {
        int n = i / (NODE_D / 4), j4 = i % (NODE_D / 4);
        cp16(kvS + (n * KD + j4 * 4) * 4,
             nbr_node + ((size_t)b * NN + n) * NODE_D + j4 * 4, true);
    }
    for (int i = t; i < NN * (EDGE_D / 4); i += 320) {
        int n = i / (EDGE_D / 4), j4 = i % (EDGE_D / 4);
        cp16(kvS + (n * KD + NODE_D + j4 * 4) * 4,
             nbr_edge + ((size_t)b * NN + n) * EDGE_D + j4 * 4, true);
    }
    for (int i = t; i < NN * (TIME_D / 4); i += 320) {
        int n = i / (TIME_D / 4), j4 = i % (TIME_D / 4);
        cp16(kvS + (n * KD + NODE_D + EDGE_D + j4 * 4) * 4,
             nbr_time + ((size_t)b * NN + n) * TIME_D + j4 * 4, true);
    }
    for (int i = t; i < QT / 4; i += 320)
        cp16(qtsS + i * 16, g_qt + (size_t)b * NPAD1 + i * 4, true);
    CP_COMMIT();
    CP_WAIT(0);
    __syncthreads();

    {
        const int n0 = 2 * w, n1 = 2 * w + 1;
        float a00 = 0.f, a01 = 0.f, a10 = 0.f, a11 = 0.f;
        for (int j = lane; j < KD; j += 32) {
            float q0 = qts[j], q1 = qts[KD + j];
            float k0 = kv[n0 * KD + j], k1 = kv[n1 * KD + j];
            a00 += q0 * k0; a01 += q0 * k1;
            a10 += q1 * k0; a11 += q1 * k1;
        }
#pragma unroll
        for (int o = 16; o; o >>= 1) {
            a00 += __shfl_xor_sync(0xffffffffu, a00, o);
            a01 += __shfl_xor_sync(0xffffffffu, a01, o);
            a10 += __shfl_xor_sync(0xffffffffu, a10, o);
            a11 += __shfl_xor_sync(0xffffffffu, a11, o);
        }
        if (lane == 0) {
            int m0 = masks[(size_t)b * NN + n0];
            int m1 = masks[(size_t)b * NN + n1];
            sc[n0]      = (m0 == 0) ? -1e10f : a00 * ATTN_SCALE;
            sc[n1]      = (m1 == 0) ? -1e10f : a01 * ATTN_SCALE;
            sc[NN + n0] = (m0 == 0) ? -1e10f : a10 * ATTN_SCALE;
            sc[NN + n1] = (m1 == 0) ? -1e10f : a11 * ATTN_SCALE;
        }
    }
    __syncthreads();

    if (w < NH) {
        const int h = w;
        float x = (lane < NN) ? sc[h * NN + lane] : -INFINITY;
        float m = x;
#pragma unroll
        for (int o = 16; o; o >>= 1) m = fmaxf(m, __shfl_xor_sync(0xffffffffu, m, o));
        float e = (lane < NN) ? __expf(x - m) : 0.f;
        float ssum = e;
#pragma unroll
        for (int o = 16; o; o >>= 1) ssum += __shfl_xor_sync(0xffffffffu, ssum, o);
        float a = e / ssum;
        if (lane < NN) {
            sc[h * NN + lane] = a;
            out[(size_t)BB * QD + ((size_t)b * NH + h) * NN + lane] = a;
        }
    }
    __syncthreads();

    for (int j = t; j < KD; j += 320) {
        float c0 = 0.f, c1 = 0.f;
#pragma unroll
        for (int n = 0; n < NN; ++n) {
            float kvv = kv[n * KD + j];
            c0 += sc[n] * kvv;
            c1 += sc[NN + n] * kvv;
        }
        __nv_bfloat16 h0 = __float2bfloat16(c0);
        __nv_bfloat16 h1 = __float2bfloat16(c1);
        size_t base = (size_t)b * KPAD2;
        g_cxh[base + j]      = h0;
        g_cxl[base + j]      = __float2bfloat16(c0 - __bfloat162float(h0));
        g_cxh[base + KD + j] = h1;
        g_cxl[base + KD + j] = __float2bfloat16(c1 - __bfloat162float(h1));
    }
    if (t < KPAD2 - QT) {
        g_cxh[(size_t)b * KPAD2 + QT + t] = __float2bfloat16(0.f);
        g_cxl[(size_t)b * KPAD2 + QT + t] = __float2bfloat16(0.f);
    }
}

// ---------------- LayerNorm, one warp per row ---------------------------------
__global__ __launch_bounds__(256)
void k_ln(const float* __restrict__ gamma, const float* __restrict__ beta,
          float* __restrict__ out)
{
    int gw   = (blockIdx.x * blockDim.x + threadIdx.x) >> 5;
    int lane = threadIdx.x & 31;
    if (gw >= BB) return;
    const float* x = g_x + (size_t)gw * QD;
    float s = 0.f, s2 = 0.f;
    for (int j = lane; j < QD; j += 32) { float v = x[j]; s += v; s2 += v * v; }
#pragma unroll
    for (int o = 16; o; o >>= 1) {
        s  += __shfl_xor_sync(0xffffffffu, s,  o);
        s2 += __shfl_xor_sync(0xffffffffu, s2, o);
    }
    float mu   = s * (1.f / QD);
    float var  = s2 * (1.f / QD) - mu * mu;
    float rstd = rsqrtf(var + LN_EPS);
    for (int j = lane; j < QD; j += 32)
        out[(size_t)gw * QD + j] = (x[j] - mu) * rstd * gamma[j] + beta[j];
}

// ---------------- launch ------------------------------------------------------
#define SMEM1 (2 * (4 * 128 * 2 * RSTR))                            // 81920
#define SMEM2 (2 * (2 * 128 * 2 * RSTR + 2 * 96 * 2 * RSTR))        // 71680

extern "C" void kernel_launch(void* const* d_in, const int* in_sizes, int n_in,
                              void* d_out, int out_size)
{
    const float* nodef    = (const float*)d_in[0];
    const float* ntime    = (const float*)d_in[1];
    const float* nbr_node = (const float*)d_in[2];
    const float* nbr_time = (const float*)d_in[3];
    const float* nbr_edge = (const float*)d_in[4];
    const int*   masks    = (const int*)  d_in[5];
    const float* Wq       = (const float*)d_in[6];
    const float* Wk       = (const float*)d_in[7];
    const float* Wv       = (const float*)d_in[8];
    const float* Wr       = (const float*)d_in[9];
    const float* br       = (const float*)d_in[10];
    const float* gamma    = (const float*)d_in[11];
    const float* beta     = (const float*)d_in[12];
    float* out = (float*)d_out;

    auto g1 = k_gemm_mma<128, NCHUNK1, KPAD1, NPAD1, false, 1>;
    auto g2 = k_gemm_mma<96,  NCHUNK2, KPAD2, QD,    true,  2>;
    cudaFuncSetAttribute(g1, cudaFuncAttributeMaxDynamicSharedMemorySize, SMEM1);
    cudaFuncSetAttribute(g2, cudaFuncAttributeMaxDynamicSharedMemorySize, SMEM2);

    k_prep_qin<<<(BB * KPAD1 + 255) / 256, 256>>>(nodef, ntime);
    k_fold_M <<<(NPAD1 * KPAD1 + 255) / 256, 256>>>(Wq, Wk);
    k_fold_Rv<<<(NPAD2 * KPAD2 + 255) / 256, 256>>>(Wr, Wv);

    dim3 grid1((BB + 127) / 128, NPAD1 / 128);
    g1<<<grid1, 256, SMEM1>>>(nodef, ntime, br);

    k_attn<<<BB, 320>>>(nbr_node, nbr_time, nbr_edge, masks, out);

    dim3 grid2((BB + 127) / 128, NPAD2 / 96);
    g2<<<grid2, 256, SMEM2>>>(nodef, ntime, br);

    k_ln<<<(BB * 32 + 255) / 256, 256>>>(gamma, beta, out);
}